// round 16
// baseline (speedup 1.0000x reference)
#include <cuda_runtime.h>
#include <cuda_bf16.h>
#include <math.h>
#include <stdint.h>

// Problem constants (fixed shapes from setup_inputs)
#define BATCH 4
#define SEQ   2048
#define DMODEL 1024
#define NHEADS 16
#define FDIM  16
#define HDIM  64
#define NTOK  (BATCH*SEQ)          // 8192
#define QKDIM (NHEADS*FDIM)        // 256
#define VDIM  (NHEADS*HDIM)        // 1024
#define FEAT  273                  // 1 + 16 + 256
#define NCHUNK 16                  // 2048 / 128
#define CHUNK 128
#define KV_ELEMS (BATCH*NHEADS*HDIM*FEAT)   // 1,118,208
#define OUT_ELEMS (NTOK*DMODEL)             // 8,388,608
#define PROW 153                   // 1 + 16 + 136 packed symmetric rows
#define SDF_P (PROW*HDIM)          // 9792
#define NRP 80                     // rowpairs in padded packed S (160 rows)
#define C2F 0.17677669529663687f   // 1/(4*sqrt(2))

// Scratch (device globals; no runtime allocation)
__device__ float g_Q[NTOK*QKDIM];
__device__ float g_K[NTOK*QKDIM];
__device__ float g_V[NTOK*VDIM];
__device__ float g_Y[NTOK*VDIM];
__device__ float g_DS[64*NCHUNK*SDF_P];          // packed chunk states
__device__ uint32_t g_SPh[64*NCHUNK*NRP*HDIM];   // prefix states, bf16 hi packed
__device__ uint32_t g_SPl[64*NCHUNK*NRP*HDIM];   // prefix states, bf16 lo packed

__device__ __forceinline__ uint32_t f2tf32(float x) {
    uint32_t u;
    asm("cvt.rna.tf32.f32 %0, %1;" : "=r"(u) : "f"(x));
    return u;
}
// HW bf16x2 pack (RNE): a -> bits[15:0], b -> bits[31:16]
__device__ __forceinline__ uint32_t pack_bf(float a, float b) {
    uint32_t r;
    asm("cvt.rn.bf16x2.f32 %0, %1, %2;" : "=r"(r) : "f"(b), "f"(a));
    return r;
}
__device__ __forceinline__ float2 unpack_bf(uint32_t p) {
    return make_float2(__uint_as_float(p << 16),
                       __uint_as_float(p & 0xFFFF0000u));
}
__device__ __forceinline__ void split_bf(float a, float b,
                                         uint32_t& h, uint32_t& l) {
    h = pack_bf(a, b);
    float2 hv = unpack_bf(h);
    l = pack_bf(a - hv.x, b - hv.y);
}
// packed index p -> (i,j), j<=i  (sqrt trick + correction)
__device__ __forceinline__ void p2ij(int p, int& i, int& j) {
    i = (int)((sqrtf(8.f * p + 1.f) - 1.f) * 0.5f);
    if ((i + 1) * (i + 2) / 2 <= p) i++;
    if (i * (i + 1) / 2 > p) i--;
    j = p - i * (i + 1) / 2;
}

#define MMA_BF16(acc_, a_, b0_, b1_)                                           \
    asm volatile(                                                              \
        "mma.sync.aligned.m16n8k16.row.col.f32.bf16.bf16.f32 "                 \
        "{%0,%1,%2,%3}, {%4,%5,%6,%7}, {%8,%9}, {%0,%1,%2,%3};"                \
        : "+f"((acc_)[0]), "+f"((acc_)[1]), "+f"((acc_)[2]), "+f"((acc_)[3])   \
        : "r"((a_)[0]), "r"((a_)[1]), "r"((a_)[2]), "r"((a_)[3]),              \
          "r"(b0_), "r"(b1_))

// ---------------------------------------------------------------------------
// tf32 GEMM (R4 design, proven)
// ---------------------------------------------------------------------------
struct GSmem {
    uint32_t As[2][16][132];
    uint32_t Bs[2][16][132];
};

__device__ __forceinline__ void gemm_tile(
    const float* __restrict__ A, const float* __restrict__ B,
    float* __restrict__ C, int N, int K, int bm, int bn, GSmem& sm) {
    const int tid  = threadIdx.x;
    const int warp = tid >> 5, lane = tid & 31;
    const int gid  = lane >> 2, tig = lane & 3;
    const int wm = (warp >> 1) * 64, wn = (warp & 1) * 64;

    const int lr = tid >> 2;
    const int kc = (tid & 3) << 2;
    const float* Ap = A + (size_t)(bm + lr) * K + kc;
    const float* Bp = B + (size_t)(bn + lr) * K + kc;
    const size_t row32 = (size_t)32 * K;

    float acc[4][8][4];
#pragma unroll
    for (int mt = 0; mt < 4; mt++)
#pragma unroll
        for (int nt = 0; nt < 8; nt++)
#pragma unroll
            for (int e = 0; e < 4; e++) acc[mt][nt][e] = 0.f;

    float4 ar[4], br[4];
#pragma unroll
    for (int p = 0; p < 4; p++) {
        ar[p] = *(const float4*)(Ap + p * row32);
        br[p] = *(const float4*)(Bp + p * row32);
    }
#pragma unroll
    for (int p = 0; p < 4; p++) {
        sm.As[0][kc + 0][lr + p * 32] = f2tf32(ar[p].x);
        sm.As[0][kc + 1][lr + p * 32] = f2tf32(ar[p].y);
        sm.As[0][kc + 2][lr + p * 32] = f2tf32(ar[p].z);
        sm.As[0][kc + 3][lr + p * 32] = f2tf32(ar[p].w);
        sm.Bs[0][kc + 0][lr + p * 32] = f2tf32(br[p].x);
        sm.Bs[0][kc + 1][lr + p * 32] = f2tf32(br[p].y);
        sm.Bs[0][kc + 2][lr + p * 32] = f2tf32(br[p].z);
        sm.Bs[0][kc + 3][lr + p * 32] = f2tf32(br[p].w);
    }
    __syncthreads();

    int cur = 0;
    for (int k0 = 0; k0 < K; k0 += 16) {
        const bool more = (k0 + 16 < K);
        if (more) {
#pragma unroll
            for (int p = 0; p < 4; p++) {
                ar[p] = *(const float4*)(Ap + k0 + 16 + p * row32);
                br[p] = *(const float4*)(Bp + k0 + 16 + p * row32);
            }
        }

#pragma unroll
        for (int ks = 0; ks < 2; ks++) {
            const int kk = ks * 8;
            uint32_t af[4][4], bf[8][2];
#pragma unroll
            for (int mt = 0; mt < 4; mt++) {
                const int m = wm + mt * 16 + gid;
                af[mt][0] = sm.As[cur][kk + tig][m];
                af[mt][1] = sm.As[cur][kk + tig][m + 8];
                af[mt][2] = sm.As[cur][kk + tig + 4][m];
                af[mt][3] = sm.As[cur][kk + tig + 4][m + 8];
            }
#pragma unroll
            for (int nt = 0; nt < 8; nt++) {
                const int n = wn + nt * 8 + gid;
                bf[nt][0] = sm.Bs[cur][kk + tig][n];
                bf[nt][1] = sm.Bs[cur][kk + tig + 4][n];
            }
#pragma unroll
            for (int mt = 0; mt < 4; mt++)
#pragma unroll
                for (int nt = 0; nt < 8; nt++) {
                    asm volatile(
                        "mma.sync.aligned.m16n8k8.row.col.f32.tf32.tf32.f32 "
                        "{%0,%1,%2,%3}, {%4,%5,%6,%7}, {%8,%9}, {%0,%1,%2,%3};"
                        : "+f"(acc[mt][nt][0]), "+f"(acc[mt][nt][1]),
                          "+f"(acc[mt][nt][2]), "+f"(acc[mt][nt][3])
                        : "r"(af[mt][0]), "r"(af[mt][1]),
                          "r"(af[mt][2]), "r"(af[mt][3]),
                          "r"(bf[nt][0]), "r"(bf[nt][1]));
                }
        }

        if (more) {
            const int nxt = cur ^ 1;
#pragma unroll
            for (int p = 0; p < 4; p++) {
                sm.As[nxt][kc + 0][lr + p * 32] = f2tf32(ar[p].x);
                sm.As[nxt][kc + 1][lr + p * 32] = f2tf32(ar[p].y);
                sm.As[nxt][kc + 2][lr + p * 32] = f2tf32(ar[p].z);
                sm.As[nxt][kc + 3][lr + p * 32] = f2tf32(ar[p].w);
                sm.Bs[nxt][kc + 0][lr + p * 32] = f2tf32(br[p].x);
                sm.Bs[nxt][kc + 1][lr + p * 32] = f2tf32(br[p].y);
                sm.Bs[nxt][kc + 2][lr + p * 32] = f2tf32(br[p].z);
                sm.Bs[nxt][kc + 3][lr + p * 32] = f2tf32(br[p].w);
            }
            __syncthreads();
        }
        cur ^= 1;
    }

#pragma unroll
    for (int mt = 0; mt < 4; mt++) {
        const int r0 = bm + wm + mt * 16 + gid;
#pragma unroll
        for (int nt = 0; nt < 8; nt++) {
            const int cc = bn + wn + nt * 8 + tig * 2;
            *(float2*)&C[(size_t)r0 * N + cc] =
                make_float2(acc[mt][nt][0], acc[mt][nt][1]);
            *(float2*)&C[(size_t)(r0 + 8) * N + cc] =
                make_float2(acc[mt][nt][2], acc[mt][nt][3]);
        }
    }
}

__global__ __launch_bounds__(128)
void tgemm_nt(const float* __restrict__ A, const float* __restrict__ B,
              float* __restrict__ C, int M, int N, int K) {
    __shared__ GSmem sm;
    gemm_tile(A, B, C, N, K, blockIdx.x * 128, blockIdx.y * 128, sm);
}

// ---------------------------------------------------------------------------
// Kernel A: per-chunk state increment via bf16x3 MMA.
// TRANSPOSED K in smem (kst[17][132]) -> LDS.64 pair loads for feature gen.
// ---------------------------------------------------------------------------
__global__ __launch_bounds__(256, 2)
void state_mma_kernel(const float* __restrict__ Km, const float* __restrict__ V,
                      float* __restrict__ DS) {
    __shared__ float kst[17][132];      // transposed k, row16 = 1.0
    __shared__ uint32_t vh[64][72];
    __shared__ uint32_t vl[64][72];
    __shared__ uchar2 ptab[136];
    const int ck = blockIdx.x, bh = blockIdx.y;
    const int b = bh >> 4, h = bh & 15;
    const int tid = threadIdx.x;
    const int warp = tid >> 5, lane = tid & 31;
    const int gid = lane >> 2, tig = lane & 3;
    const int wr = warp >> 2, wc = warp & 3;
    const int tokb = b * SEQ + ck * CHUNK;

    // stage K transposed
    for (int t = tid; t < 512; t += 256) {
        int r = t >> 2, c4 = (t & 3) << 2;
        float4 kv = *(const float4*)&Km[(size_t)(tokb + r) * QKDIM + h * FDIM + c4];
        kst[c4 + 0][r] = kv.x; kst[c4 + 1][r] = kv.y;
        kst[c4 + 2][r] = kv.z; kst[c4 + 3][r] = kv.w;
    }
    if (tid < 128) kst[16][tid] = 1.0f;
    // stage V packed bf16 token-pairs (hi/lo)
    for (int t = tid; t < 1024; t += 256) {
        int kp = t >> 4, c4 = (t & 15) << 2;
        float4 a = *(const float4*)&V[(size_t)(tokb + 2 * kp) * VDIM + h * HDIM + c4];
        float4 bb = *(const float4*)&V[(size_t)(tokb + 2 * kp + 1) * VDIM + h * HDIM + c4];
        const float av[4] = {a.x, a.y, a.z, a.w};
        const float bv[4] = {bb.x, bb.y, bb.z, bb.w};
#pragma unroll
        for (int e = 0; e < 4; e++) {
            uint32_t hp, lp;
            split_bf(av[e], bv[e], hp, lp);
            vh[kp][c4 + e] = hp;
            vl[kp][c4 + e] = lp;
        }
    }
    if (tid < 136) {
        int i, j;
        p2ij(tid, i, j);
        ptab[tid] = make_uchar2((unsigned char)i, (unsigned char)j);
    }
    __syncthreads();

    int ia[5][2], ja[5][2];
    float wt[5][2];
#pragma unroll
    for (int mt = 0; mt < 5; mt++) {
#pragma unroll
        for (int hw = 0; hw < 2; hw++) {
            const int row = wr * 80 + mt * 16 + gid + hw * 8;
            int i, j; float w;
            if (row == 0)        { i = 16; j = 16; w = 1.f; }
            else if (row < 17)   { i = row - 1; j = 16; w = 0.5f; }
            else if (row < PROW) { uchar2 p = ptab[row - 17]; i = p.x; j = p.y; w = C2F; }
            else                 { i = 16; j = 16; w = 0.f; }
            ia[mt][hw] = i; ja[mt][hw] = j; wt[mt][hw] = w;
        }
    }

    float acc[5][2][4];
#pragma unroll
    for (int mt = 0; mt < 5; mt++)
#pragma unroll
        for (int nt = 0; nt < 2; nt++)
#pragma unroll
            for (int e = 0; e < 4; e++) acc[mt][nt][e] = 0.f;

    for (int kss = 0; kss < 8; kss++) {
        uint32_t b_h0[2], b_h1[2], b_l0[2], b_l1[2];
#pragma unroll
        for (int nt = 0; nt < 2; nt++) {
            const int n = wc * 16 + nt * 8 + gid;
            b_h0[nt] = vh[kss * 8 + tig][n];
            b_h1[nt] = vh[kss * 8 + tig + 4][n];
            b_l0[nt] = vl[kss * 8 + tig][n];
            b_l1[nt] = vl[kss * 8 + tig + 4][n];
        }
        const int t0 = kss * 16 + 2 * tig;
        const int t2 = t0 + 8;
#pragma unroll
        for (int mt = 0; mt < 5; mt++) {
            const int i0 = ia[mt][0], j0 = ja[mt][0];
            const int i1 = ia[mt][1], j1 = ja[mt][1];
            const float w0 = wt[mt][0], w1 = wt[mt][1];
            float2 ai0 = *(const float2*)&kst[i0][t0];
            float2 aj0 = *(const float2*)&kst[j0][t0];
            float2 bi0 = *(const float2*)&kst[i0][t2];
            float2 bj0 = *(const float2*)&kst[j0][t2];
            float2 ai1 = *(const float2*)&kst[i1][t0];
            float2 aj1 = *(const float2*)&kst[j1][t0];
            float2 bi1 = *(const float2*)&kst[i1][t2];
            float2 bj1 = *(const float2*)&kst[j1][t2];
            float f00 = w0 * ai0.x * aj0.x, f01 = w0 * ai0.y * aj0.y;
            float f02 = w0 * bi0.x * bj0.x, f03 = w0 * bi0.y * bj0.y;
            float f10 = w1 * ai1.x * aj1.x, f11 = w1 * ai1.y * aj1.y;
            float f12 = w1 * bi1.x * bj1.x, f13 = w1 * bi1.y * bj1.y;
            uint32_t ah[4], al[4];
            split_bf(f00, f01, ah[0], al[0]);
            split_bf(f10, f11, ah[1], al[1]);
            split_bf(f02, f03, ah[2], al[2]);
            split_bf(f12, f13, ah[3], al[3]);
#pragma unroll
            for (int nt = 0; nt < 2; nt++) {
                MMA_BF16(acc[mt][nt], ah, b_h0[nt], b_h1[nt]);
                MMA_BF16(acc[mt][nt], ah, b_l0[nt], b_l1[nt]);
                MMA_BF16(acc[mt][nt], al, b_h0[nt], b_h1[nt]);
            }
        }
    }

    float* base = DS + (size_t)(bh * NCHUNK + ck) * SDF_P;
#pragma unroll
    for (int mt = 0; mt < 5; mt++) {
        const int ra = wr * 80 + mt * 16 + gid;
        const int rb = ra + 8;
#pragma unroll
        for (int nt = 0; nt < 2; nt++) {
            const int n = wc * 16 + nt * 8 + tig * 2;
            if (ra < PROW)
                *(float2*)&base[ra * HDIM + n] =
                    make_float2(acc[mt][nt][0], acc[mt][nt][1]);
            if (rb < PROW)
                *(float2*)&base[rb * HDIM + n] =
                    make_float2(acc[mt][nt][2], acc[mt][nt][3]);
        }
    }
}

// ---------------------------------------------------------------------------
// Kernel B: exclusive scan over packed rows; output PRE-SPLIT packed bf16
// hi/lo rowpair tiles (zero-padded to NRP=80 rowpairs). kv_state mirrored.
// thread = (rowpair rp 0..79, colgroup 0..15 of 4)
// ---------------------------------------------------------------------------
__global__ void scan_kernel(const float* __restrict__ DS,
                            uint32_t* __restrict__ SPh,
                            uint32_t* __restrict__ SPl,
                            float* __restrict__ kv_out) {
    const int bh = blockIdx.y;
    const int idx = blockIdx.x * 256 + threadIdx.x;
    if (idx >= NRP * 16) return;
    const int rp = idx >> 4, f0 = (idx & 15) * 4;
    const int dp0 = 2 * rp, dp1 = 2 * rp + 1;

    int pi0 = 0, pj0 = 0, pi1 = 0, pj1 = 0;
    float s0 = 1.f, s1 = 1.f;
    if (dp0 >= 17 && dp0 < PROW) {
        p2ij(dp0 - 17, pi0, pj0);
        s0 = (pi0 == pj0) ? 1.f : 2.f;
    }
    if (dp1 >= 17 && dp1 < PROW) {
        p2ij(dp1 - 17, pi1, pj1);
        s1 = (pi1 == pj1) ? 1.f : 2.f;
    }
    const bool v0ok = (dp0 < PROW), v1ok = (dp1 < PROW);

    const float* src0 = DS + (size_t)bh * NCHUNK * SDF_P + (size_t)dp0 * HDIM + f0;
    const float* src1 = DS + (size_t)bh * NCHUNK * SDF_P + (size_t)dp1 * HDIM + f0;
    uint32_t* dh = SPh + (size_t)bh * NCHUNK * NRP * HDIM + rp * HDIM + f0;
    uint32_t* dl = SPl + (size_t)bh * NCHUNK * NRP * HDIM + rp * HDIM + f0;

    float r0[4] = {0.f, 0.f, 0.f, 0.f};
    float r1[4] = {0.f, 0.f, 0.f, 0.f};
#pragma unroll
    for (int c = 0; c < NCHUNK; c++) {
        float4 v0 = v0ok ? *(const float4*)(src0 + (size_t)c * SDF_P)
                         : make_float4(0.f, 0.f, 0.f, 0.f);
        float4 v1 = v1ok ? *(const float4*)(src1 + (size_t)c * SDF_P)
                         : make_float4(0.f, 0.f, 0.f, 0.f);
        const size_t ofs = (size_t)c * NRP * HDIM;
#pragma unroll
        for (int e = 0; e < 4; e++) {
            uint32_t hp, lp;
            split_bf(r0[e] * s0, r1[e] * s1, hp, lp);
            dh[ofs + e] = hp;
            dl[ofs + e] = lp;
        }
        r0[0] += v0.x; r0[1] += v0.y; r0[2] += v0.z; r0[3] += v0.w;
        r1[0] += v1.x; r1[1] += v1.y; r1[2] += v1.z; r1[3] += v1.w;
    }
    if (kv_out) {
        float* kb = kv_out + (size_t)bh * (HDIM * FEAT);
        if (v0ok) {
            if (dp0 < 17) {
#pragma unroll
                for (int ff = 0; ff < 4; ff++)
                    kb[(size_t)(f0 + ff) * FEAT + dp0] = r0[ff];
            } else {
                const int d1 = 17 + pi0 * 16 + pj0, d2 = 17 + pj0 * 16 + pi0;
#pragma unroll
                for (int ff = 0; ff < 4; ff++) {
                    kb[(size_t)(f0 + ff) * FEAT + d1] = r0[ff];
                    kb[(size_t)(f0 + ff) * FEAT + d2] = r0[ff];
                }
            }
        }
        if (v1ok) {
            if (dp1 < 17) {
#pragma unroll
                for (int ff = 0; ff < 4; ff++)
                    kb[(size_t)(f0 + ff) * FEAT + dp1] = r1[ff];
            } else {
                const int d1 = 17 + pi1 * 16 + pj1, d2 = 17 + pj1 * 16 + pi1;
#pragma unroll
                for (int ff = 0; ff < 4; ff++) {
                    kb[(size_t)(f0 + ff) * FEAT + d1] = r1[ff];
                    kb[(size_t)(f0 + ff) * FEAT + d2] = r1[ff];
                }
            }
        }
    }
}

// ---------------------------------------------------------------------------
// Kernel C: inter-chunk bf16x3 MMA over pre-split packed S (10 k-steps) +
// intra-chunk causal via two-stage MMA, RMSNorm + g.
// ---------------------------------------------------------------------------
#define AK_QS(r,c)     dyn[(r)*17+(c)]                 // q*SC, col16 = 1.0
#define ATTN_SMEM      (16064*4)                       // 64,256 bytes
#define AK_SHW(b,rp,n) shw[(b)*576+(rp)*72+(n)]
#define AK_SLW(b,rp,n) slw[(b)*576+(rp)*72+(n)]

__device__ __forceinline__ float qfeatp(const float* dyn, const uchar2* ptab,
                                        int r, int d) {
    if (d == 0) return 1.0f;
    if (d < 17) return AK_QS(r, d - 1) * 1.1892071150027210f;   // 0.5/SC folded
    if (d < PROW) {
        const uchar2 ij = ptab[d - 17];
        return AK_QS(r, ij.x) * AK_QS(r, ij.y);
    }
    return 0.f;
}

__global__ __launch_bounds__(256, 2)
void attn_out_kernel(const float* __restrict__ Q, const float* __restrict__ Km,
                     const float* __restrict__ V,
                     const uint32_t* __restrict__ SPh,
                     const uint32_t* __restrict__ SPl,
                     const float* __restrict__ g, float* __restrict__ Y) {
    extern __shared__ float dyn[];
    __shared__ uchar2 ptab[136];
    uint32_t* kh = (uint32_t*)(dyn + 2176);    // [128][9]
    uint32_t* kl = (uint32_t*)(dyn + 3328);    // [128][9]
    uint32_t* vh = (uint32_t*)(dyn + 4480);    // [64][72]
    uint32_t* vl = (uint32_t*)(dyn + 9088);    // [64][72]
    uint32_t* shw = (uint32_t*)(dyn + 13696);
    uint32_t* slw = (uint32_t*)(dyn + 14848);
    float* gs = dyn + 16000;
    const int ck = blockIdx.x;
    const int bh = blockIdx.y;
    const int b = bh >> 4, h = bh & 15;
    const int tid = threadIdx.x;
    const int warp = tid >> 5, lane = tid & 31;
    const int gid = lane >> 2, tig = lane & 3;
    const int tok0 = b * SEQ + ck * CHUNK;
    const float SC  = 0.4204482076268573f;    // sqrt(1/(4*sqrt2))
    const float DOT = 2.3784142300054421f;    // 1/SC
    const uint32_t* Sph = SPh + (size_t)(bh * NCHUNK + ck) * NRP * HDIM;
    const uint32_t* Spl = SPl + (size_t)(bh * NCHUNK + ck) * NRP * HDIM;

    // ---- stage Q (scaled, padded) + K (packed bf16 dim-pairs, stride 9) ----
    for (int t = tid; t < 512; t += 256) {
        int r = t >> 2, c4 = (t & 3) << 2;
        float4 qv = *(const float4*)&Q[(size_t)(tok0 + r) * QKDIM + h * FDIM + c4];
        AK_QS(r, c4 + 0) = qv.x * SC; AK_QS(r, c4 + 1) = qv.y * SC;
        AK_QS(r, c4 + 2) = qv.z * SC; AK_QS(r, c4 + 3) = qv.w * SC;
        float4 kv = *(const float4*)&Km[(size_t)(tok0 + r) * QKDIM + h * FDIM + c4];
        uint32_t hp, lp;
        split_bf(kv.x, kv.y, hp, lp);
        kh[r * 9 + (c4 >> 1)] = hp; kl[r * 9 + (c4 >> 1)] = lp;
        split_bf(kv.z, kv.w, hp, lp);
        kh[r * 9 + (c4 >> 1) + 1] = hp; kl[r * 9 + (c4 >> 1) + 1] = lp;
    }
    if (tid < 128) AK_QS(tid, 16) = 1.0f;
    // ---- stage V packed bf16 token-pairs (hi/lo) ----
    for (int t = tid; t < 1024; t += 256) {
        int kp = t >> 4, c4 = (t & 15) << 2;
        float4 a = *(const float4*)&V[(size_t)(tok0 + 2 * kp) * VDIM + h * HDIM + c4];
        float4 bb = *(const float4*)&V[(size_t)(tok0 + 2 * kp + 1) * VDIM + h * HDIM + c4];
        const float av[4] = {a.x, a.y, a.z, a.w};
        const float bv[4] = {bb.x, bb.y, bb.z, bb.w};
#pragma unroll
        for (int e = 0; e < 4; e++) {
            uint32_t hp, lp;
            split_bf(av[e], bv[e], hp, lp);
            vh[kp * 72 + c4 + e] = hp;
            vl[kp * 72 + c4 + e] = lp;
        }
    }
    if (tid < 64) gs[tid] = g[tid];
    if (tid < 136) {
        int i, j;
        p2ij(tid, i, j);
        ptab[tid] = make_uchar2((unsigned char)i, (unsigned char)j);
    }
    {   // S tile for step 0 (rowpairs 0..7) — direct packed copy
#pragma unroll
        for (int q = 0; q < 2; q++) {
            const int id = tid + q * 256;
            const int rp = id >> 6, n = id & 63;
            AK_SHW(0, rp, n) = Sph[rp * HDIM + n];
            AK_SLW(0, rp, n) = Spl[rp * HDIM + n];
        }
    }
    __syncthreads();

    float acc[8][4];
#pragma unroll
    for (int nt = 0; nt < 8; nt++)
#pragma unroll
        for (int e = 0; e < 4; e++) acc[nt][e] = 0.f;

    const int r0 = warp * 16 + gid;
    const int r1 = r0 + 8;

    // ---- inter-chunk: y += qf @ S_packed via bf16x3 MMA, 10 k-steps ----
    int buf = 0;
    for (int s = 0; s < 10; s++) {
        uint32_t pAh = 0, pAl = 0, pBh = 0, pBl = 0;
        int rpA = 0, nA = 0, rpB = 0, nB = 0;
        if (s < 9) {
            const int rb = 8 * (s + 1);
            int idA = tid;           rpA = idA >> 6; nA = idA & 63;
            int idB = tid + 256;     rpB = idB >> 6; nB = idB & 63;
            pAh = Sph[(rb + rpA) * HDIM + nA];
            pAl = Spl[(rb + rpA) * HDIM + nA];
            pBh = Sph[(rb + rpB) * HDIM + nB];
            pBl = Spl[(rb + rpB) * HDIM + nB];
        }
        const int da = 16 * s + 2 * tig;
        const int db = da + 8;
        float f00 = qfeatp(dyn, ptab, r0, da),  f01 = qfeatp(dyn, ptab, r0, da + 1);
        float f10 = qfeatp(dyn, ptab, r1, da),  f11 = qfeatp(dyn, ptab, r1, da + 1);
        float f02 = qfeatp(dyn, ptab, r0, db),  f03 = qfeatp(dyn, ptab, r0, db + 1);
        float f12 = qfeatp(dyn, ptab, r1, db),  f13 = qfeatp(dyn, ptab, r1, db + 1);
        uint32_t ah[4], al[4];
        split_bf(f00, f01, ah[0], al[0]);
        split_bf(f10, f11, ah[1], al[1]);
        split_bf(f02, f03, ah[2], al[2]);
        split_bf(f12, f13, ah[3], al[3]);
#pragma unroll
        for (int nt = 0; nt < 8; nt++) {
            const int n = nt * 8 + gid;
            uint32_t bh0 = AK_SHW(buf, tig, n);
            uint32_t bh1 = AK_SHW(buf, tig + 4, n);
            uint32_t bl0 = AK_SLW(buf, tig, n);
            uint32_t bl1 = AK_SLW(buf, tig + 4, n);
            MMA_BF16(acc[nt], ah, bh0, bh1);
            MMA_BF16(acc[nt], ah, bl0, bl1);
            MMA_BF16(acc[nt], al, bh0, bh1);
        }
        if (s < 9) {
            const int nb = buf ^ 1;
            AK_SHW(nb, rpA, nA) = pAh;
            AK_SLW(nb, rpA, nA) = pAl;
            AK_SHW(nb, rpB, nB) = pBh;
            AK_SLW(nb, rpB, nB) = pBl;
            __syncthreads();
            buf = nb;
        }
    }

    // ---- intra-chunk causal via MMA: scores -> poly/mask -> P@V ----
    uint32_t qah[4], qal[4];
    split_bf(AK_QS(r0, 2 * tig),     AK_QS(r0, 2 * tig + 1),     qah[0], qal[0]);
    split_bf(AK_QS(r1, 2 * tig),     AK_QS(r1, 2 * tig + 1),     qah[1], qal[1]);
    split_bf(AK_QS(r0, 2 * tig + 8), AK_QS(r0, 2 * tig + 9),     qah[2], qal[2]);
    split_bf(AK_QS(r1, 2 * tig + 8), AK_QS(r1, 2 * tig + 9),     qah[3], qal[3]);

    for (int s = 0; s <= warp; s++) {
        float sc[2][4];
#pragma unroll
        for (int tt = 0; tt < 2; tt++) {
#pragma unroll
            for (int e = 0; e < 4; e++) sc[tt][e] = 0.f;
            const int tokbase = s * 16 + tt * 8;
            uint32_t bh0 = kh[(tokbase + gid) * 9 + tig];
            uint32_t bh1 = kh[(tokbase + gid) * 9 + tig + 4];
            uint32_t bl0 = kl[(tokbase + gid) * 9 + tig];
            uint32_t bl1 = kl[(tokbase + gid) * 9 + tig + 4];
            MMA_BF16(sc[tt], qah, bh0, bh1);
            MMA_BF16(sc[tt], qah, bl0, bl1);
            MMA_BF16(sc[tt], qal, bh0, bh1);
        }
        const bool diag = (s == warp);
#pragma unroll
        for (int tt = 0; tt < 2; tt++)
#pragma unroll
            for (int e = 0; e < 4; e++) {
                const float sd = sc[tt][e] * DOT;
                float A = fmaf(sd, 0.25f, 1.0f);
                A = fmaf(sd * sd, 0.03125f, A);
                if (diag) {
                    const int tok = tt * 8 + 2 * tig + (e & 1);
                    const int row = gid + ((e >> 1) << 3);
                    A = (tok <= row) ? A : 0.f;
                }
                sc[tt][e] = A;
            }
        uint32_t pah[4], pal[4];
        split_bf(sc[0][0], sc[0][1], pah[0], pal[0]);
        split_bf(sc[0][2], sc[0][3], pah[1], pal[1]);
        split_bf(sc[1][0], sc[1][1], pah[2], pal[2]);
        split_bf(sc[1][2], sc[1][3], pah[3], pal[3]);
#pragma unroll
        for (int ft = 0; ft < 8; ft++) {
            const int f = ft * 8 + gid;
            uint32_t vb0 = vh[(s * 8 + tig) * 72 + f];
            uint32_t vb1 = vh[(s * 8 + tig + 4) * 72 + f];
            uint32_t vc0 = vl[(s * 8 + tig) * 72 + f];
            uint32_t vc1 = vl[(s * 8 + tig + 4) * 72 + f];
            MMA_BF16(acc[ft], pah, vb0, vb1);
            MMA_BF16(acc[ft], pah, vc0, vc1);
            MMA_BF16(acc[ft], pal, vb0, vb1);
        }
    }

    // ---- RMSNorm (reduce across tig lanes) + gate + store ----
    float ss0 = 0.f, ss1 = 0.f;
#pragma unroll
    for (int nt = 0; nt < 8; nt++) {
        ss0 = fmaf(acc[nt][0], acc[nt][0], ss0);
        ss0 = fmaf(acc[nt][1], acc[nt][1], ss0);
        ss1 = fmaf(acc[nt][2], acc[nt][2], ss1);
        ss1 = fmaf(acc[nt][3], acc[nt][3], ss1);
    }
    ss0 += __shfl_xor_sync(0xffffffffu, ss0, 1);
    ss0 += __shfl_xor_sync(0xffffffffu, ss0, 2);
    ss1 += __shfl_xor_sync(0xffffffffu, ss1, 1);
    ss1 += __shfl_xor_sync(0xffffffffu, ss1, 2);
    const float rms0 = rsqrtf(ss0 * (1.0f / 64.0f) + 1e-5f);
    const float rms1 = rsqrtf(ss1 * (1.0f / 64.0f) + 1e-5f);
    float* y0 = Y + (size_t)(tok0 + r0) * VDIM + h * HDIM;
    float* y1 = Y + (size_t)(tok0 + r1) * VDIM + h * HDIM;
#pragma unroll
    for (int nt = 0; nt < 8; nt++) {
        const int c = nt * 8 + tig * 2;
        float2 o0, o1;
        o0.x = acc[nt][0] * rms0 * gs[c];
        o0.y = acc[nt][1] * rms0 * gs[c + 1];
        o1.x = acc[nt][2] * rms1 * gs[c];
        o1.y = acc[nt][3] * rms1 * gs[c + 1];
        *(float2*)&y0[c] = o0;
        *(float2*)&y1[c] = o1;
    }
}

// ---------------------------------------------------------------------------
extern "C" void kernel_launch(void* const* d_in, const int* in_sizes, int n_in,
                              void* d_out, int out_size) {
    const float* X  = (const float*)d_in[0];
    const float* Wq = (const float*)d_in[1];
    const float* Wk = (const float*)d_in[2];
    const float* Wv = (const float*)d_in[3];
    const float* Wo = (const float*)d_in[4];
    const float* g  = (const float*)d_in[5];
    float* out = (float*)d_out;

    float *Qb, *Kb, *Vb, *Yb, *Sb;
    uint32_t *SPhb, *SPlb;
    cudaGetSymbolAddress((void**)&Qb, g_Q);
    cudaGetSymbolAddress((void**)&Kb, g_K);
    cudaGetSymbolAddress((void**)&Vb, g_V);
    cudaGetSymbolAddress((void**)&Yb, g_Y);
    cudaGetSymbolAddress((void**)&Sb, g_DS);
    cudaGetSymbolAddress((void**)&SPhb, g_SPh);
    cudaGetSymbolAddress((void**)&SPlb, g_SPl);

    static int attn_smem_set = 0;
    if (!attn_smem_set) {
        cudaFuncSetAttribute(attn_out_kernel,
                             cudaFuncAttributeMaxDynamicSharedMemorySize,
                             ATTN_SMEM);
        attn_smem_set = 1;
    }

    // Projections (separate launches — proven fastest config)
    tgemm_nt<<<dim3(NTOK / 128, QKDIM / 128), 128>>>(X, Wq, Qb, NTOK, QKDIM, DMODEL);
    tgemm_nt<<<dim3(NTOK / 128, QKDIM / 128), 128>>>(X, Wk, Kb, NTOK, QKDIM, DMODEL);
    tgemm_nt<<<dim3(NTOK / 128, VDIM / 128),  128>>>(X, Wv, Vb, NTOK, VDIM,  DMODEL);

    // Chunked linear attention (packed symmetric states, all-MMA)
    float* kv_out = (out_size >= OUT_ELEMS + KV_ELEMS) ? (out + OUT_ELEMS) : nullptr;
    state_mma_kernel<<<dim3(NCHUNK, BATCH * NHEADS), 256>>>(Kb, Vb, Sb);
    scan_kernel<<<dim3((NRP * 16 + 255) / 256, BATCH * NHEADS), 256>>>(
        Sb, SPhb, SPlb, kv_out);
    attn_out_kernel<<<dim3(NCHUNK, BATCH * NHEADS), 256, ATTN_SMEM>>>(
        Qb, Kb, Vb, SPhb, SPlb, g, Yb);

    // Output projection
    tgemm_nt<<<dim3(NTOK / 128, DMODEL / 128), 128>>>(Yb, Wo, out, NTOK, DMODEL, DMODEL);
}

// round 17
// speedup vs baseline: 1.0269x; 1.0269x over previous
#include <cuda_runtime.h>
#include <cuda_bf16.h>
#include <math.h>
#include <stdint.h>

// Problem constants (fixed shapes from setup_inputs)
#define BATCH 4
#define SEQ   2048
#define DMODEL 1024
#define NHEADS 16
#define FDIM  16
#define HDIM  64
#define NTOK  (BATCH*SEQ)          // 8192
#define QKDIM (NHEADS*FDIM)        // 256
#define VDIM  (NHEADS*HDIM)        // 1024
#define FEAT  273                  // 1 + 16 + 256
#define NCHUNK 16                  // 2048 / 128
#define CHUNK 128
#define KV_ELEMS (BATCH*NHEADS*HDIM*FEAT)   // 1,118,208
#define OUT_ELEMS (NTOK*DMODEL)             // 8,388,608
#define PROW 153                   // 1 + 16 + 136 packed symmetric rows
#define SDF_P (PROW*HDIM)          // 9792
#define C2F 0.17677669529663687f   // 1/(4*sqrt(2))

// Scratch (device globals; no runtime allocation)
__device__ float g_Q[NTOK*QKDIM];
__device__ float g_K[NTOK*QKDIM];
__device__ float g_V[NTOK*VDIM];
__device__ float g_Y[NTOK*VDIM];
__device__ float g_DS[64*NCHUNK*SDF_P];   // packed chunk states (state out)
__device__ float g_SP[64*NCHUNK*SDF_P];   // packed exclusive-prefix states

__device__ __forceinline__ uint32_t f2tf32(float x) {
    uint32_t u;
    asm("cvt.rna.tf32.f32 %0, %1;" : "=r"(u) : "f"(x));
    return u;
}
// HW bf16x2 pack (RNE): a -> bits[15:0], b -> bits[31:16]
__device__ __forceinline__ uint32_t pack_bf(float a, float b) {
    uint32_t r;
    asm("cvt.rn.bf16x2.f32 %0, %1, %2;" : "=r"(r) : "f"(b), "f"(a));
    return r;
}
__device__ __forceinline__ float2 unpack_bf(uint32_t p) {
    return make_float2(__uint_as_float(p << 16),
                       __uint_as_float(p & 0xFFFF0000u));
}
__device__ __forceinline__ void split_bf(float a, float b,
                                         uint32_t& h, uint32_t& l) {
    h = pack_bf(a, b);
    float2 hv = unpack_bf(h);
    l = pack_bf(a - hv.x, b - hv.y);
}
// packed index p -> (i,j), j<=i  (sqrt trick + correction)
__device__ __forceinline__ void p2ij(int p, int& i, int& j) {
    i = (int)((sqrtf(8.f * p + 1.f) - 1.f) * 0.5f);
    if ((i + 1) * (i + 2) / 2 <= p) i++;
    if (i * (i + 1) / 2 > p) i--;
    j = p - i * (i + 1) / 2;
}

#define MMA_BF16(acc_, a_, b0_, b1_)                                           \
    asm volatile(                                                              \
        "mma.sync.aligned.m16n8k16.row.col.f32.bf16.bf16.f32 "                 \
        "{%0,%1,%2,%3}, {%4,%5,%6,%7}, {%8,%9}, {%0,%1,%2,%3};"                \
        : "+f"((acc_)[0]), "+f"((acc_)[1]), "+f"((acc_)[2]), "+f"((acc_)[3])   \
        : "r"((a_)[0]), "r"((a_)[1]), "r"((a_)[2]), "r"((a_)[3]),              \
          "r"(b0_), "r"(b1_))

// ---------------------------------------------------------------------------
// tf32 GEMM (R4 design, proven)
// ---------------------------------------------------------------------------
struct GSmem {
    uint32_t As[2][16][132];
    uint32_t Bs[2][16][132];
};

__device__ __forceinline__ void gemm_tile(
    const float* __restrict__ A, const float* __restrict__ B,
    float* __restrict__ C, int N, int K, int bm, int bn, GSmem& sm) {
    const int tid  = threadIdx.x;
    const int warp = tid >> 5, lane = tid & 31;
    const int gid  = lane >> 2, tig = lane & 3;
    const int wm = (warp >> 1) * 64, wn = (warp & 1) * 64;

    const int lr = tid >> 2;
    const int kc = (tid & 3) << 2;
    const float* Ap = A + (size_t)(bm + lr) * K + kc;
    const float* Bp = B + (size_t)(bn + lr) * K + kc;
    const size_t row32 = (size_t)32 * K;

    float acc[4][8][4];
#pragma unroll
    for (int mt = 0; mt < 4; mt++)
#pragma unroll
        for (int nt = 0; nt < 8; nt++)
#pragma unroll
            for (int e = 0; e < 4; e++) acc[mt][nt][e] = 0.f;

    float4 ar[4], br[4];
#pragma unroll
    for (int p = 0; p < 4; p++) {
        ar[p] = *(const float4*)(Ap + p * row32);
        br[p] = *(const float4*)(Bp + p * row32);
    }
#pragma unroll
    for (int p = 0; p < 4; p++) {
        sm.As[0][kc + 0][lr + p * 32] = f2tf32(ar[p].x);
        sm.As[0][kc + 1][lr + p * 32] = f2tf32(ar[p].y);
        sm.As[0][kc + 2][lr + p * 32] = f2tf32(ar[p].z);
        sm.As[0][kc + 3][lr + p * 32] = f2tf32(ar[p].w);
        sm.Bs[0][kc + 0][lr + p * 32] = f2tf32(br[p].x);
        sm.Bs[0][kc + 1][lr + p * 32] = f2tf32(br[p].y);
        sm.Bs[0][kc + 2][lr + p * 32] = f2tf32(br[p].z);
        sm.Bs[0][kc + 3][lr + p * 32] = f2tf32(br[p].w);
    }
    __syncthreads();

    int cur = 0;
    for (int k0 = 0; k0 < K; k0 += 16) {
        const bool more = (k0 + 16 < K);
        if (more) {
#pragma unroll
            for (int p = 0; p < 4; p++) {
                ar[p] = *(const float4*)(Ap + k0 + 16 + p * row32);
                br[p] = *(const float4*)(Bp + k0 + 16 + p * row32);
            }
        }

#pragma unroll
        for (int ks = 0; ks < 2; ks++) {
            const int kk = ks * 8;
            uint32_t af[4][4], bf[8][2];
#pragma unroll
            for (int mt = 0; mt < 4; mt++) {
                const int m = wm + mt * 16 + gid;
                af[mt][0] = sm.As[cur][kk + tig][m];
                af[mt][1] = sm.As[cur][kk + tig][m + 8];
                af[mt][2] = sm.As[cur][kk + tig + 4][m];
                af[mt][3] = sm.As[cur][kk + tig + 4][m + 8];
            }
#pragma unroll
            for (int nt = 0; nt < 8; nt++) {
                const int n = wn + nt * 8 + gid;
                bf[nt][0] = sm.Bs[cur][kk + tig][n];
                bf[nt][1] = sm.Bs[cur][kk + tig + 4][n];
            }
#pragma unroll
            for (int mt = 0; mt < 4; mt++)
#pragma unroll
                for (int nt = 0; nt < 8; nt++) {
                    asm volatile(
                        "mma.sync.aligned.m16n8k8.row.col.f32.tf32.tf32.f32 "
                        "{%0,%1,%2,%3}, {%4,%5,%6,%7}, {%8,%9}, {%0,%1,%2,%3};"
                        : "+f"(acc[mt][nt][0]), "+f"(acc[mt][nt][1]),
                          "+f"(acc[mt][nt][2]), "+f"(acc[mt][nt][3])
                        : "r"(af[mt][0]), "r"(af[mt][1]),
                          "r"(af[mt][2]), "r"(af[mt][3]),
                          "r"(bf[nt][0]), "r"(bf[nt][1]));
                }
        }

        if (more) {
            const int nxt = cur ^ 1;
#pragma unroll
            for (int p = 0; p < 4; p++) {
                sm.As[nxt][kc + 0][lr + p * 32] = f2tf32(ar[p].x);
                sm.As[nxt][kc + 1][lr + p * 32] = f2tf32(ar[p].y);
                sm.As[nxt][kc + 2][lr + p * 32] = f2tf32(ar[p].z);
                sm.As[nxt][kc + 3][lr + p * 32] = f2tf32(ar[p].w);
                sm.Bs[nxt][kc + 0][lr + p * 32] = f2tf32(br[p].x);
                sm.Bs[nxt][kc + 1][lr + p * 32] = f2tf32(br[p].y);
                sm.Bs[nxt][kc + 2][lr + p * 32] = f2tf32(br[p].z);
                sm.Bs[nxt][kc + 3][lr + p * 32] = f2tf32(br[p].w);
            }
            __syncthreads();
        }
        cur ^= 1;
    }

#pragma unroll
    for (int mt = 0; mt < 4; mt++) {
        const int r0 = bm + wm + mt * 16 + gid;
#pragma unroll
        for (int nt = 0; nt < 8; nt++) {
            const int cc = bn + wn + nt * 8 + tig * 2;
            *(float2*)&C[(size_t)r0 * N + cc] =
                make_float2(acc[mt][nt][0], acc[mt][nt][1]);
            *(float2*)&C[(size_t)(r0 + 8) * N + cc] =
                make_float2(acc[mt][nt][2], acc[mt][nt][3]);
        }
    }
}

__global__ __launch_bounds__(128)
void tgemm_nt(const float* __restrict__ A, const float* __restrict__ B,
              float* __restrict__ C, int M, int N, int K) {
    __shared__ GSmem sm;
    gemm_tile(A, B, C, N, K, blockIdx.x * 128, blockIdx.y * 128, sm);
}

// ---------------------------------------------------------------------------
// Kernel A: per-chunk state increment via bf16x3 MMA.
// TRANSPOSED K in smem (kst[17][132]) -> LDS.64 pair loads (R16 measured win).
// ---------------------------------------------------------------------------
__global__ __launch_bounds__(256, 2)
void state_mma_kernel(const float* __restrict__ Km, const float* __restrict__ V,
                      float* __restrict__ DS) {
    __shared__ float kst[17][132];      // transposed k, row16 = 1.0
    __shared__ uint32_t vh[64][72];
    __shared__ uint32_t vl[64][72];
    __shared__ uchar2 ptab[136];
    const int ck = blockIdx.x, bh = blockIdx.y;
    const int b = bh >> 4, h = bh & 15;
    const int tid = threadIdx.x;
    const int warp = tid >> 5, lane = tid & 31;
    const int gid = lane >> 2, tig = lane & 3;
    const int wr = warp >> 2, wc = warp & 3;
    const int tokb = b * SEQ + ck * CHUNK;

    // stage K transposed
    for (int t = tid; t < 512; t += 256) {
        int r = t >> 2, c4 = (t & 3) << 2;
        float4 kv = *(const float4*)&Km[(size_t)(tokb + r) * QKDIM + h * FDIM + c4];
        kst[c4 + 0][r] = kv.x; kst[c4 + 1][r] = kv.y;
        kst[c4 + 2][r] = kv.z; kst[c4 + 3][r] = kv.w;
    }
    if (tid < 128) kst[16][tid] = 1.0f;
    // stage V packed bf16 token-pairs (hi/lo)
    for (int t = tid; t < 1024; t += 256) {
        int kp = t >> 4, c4 = (t & 15) << 2;
        float4 a = *(const float4*)&V[(size_t)(tokb + 2 * kp) * VDIM + h * HDIM + c4];
        float4 bb = *(const float4*)&V[(size_t)(tokb + 2 * kp + 1) * VDIM + h * HDIM + c4];
        const float av[4] = {a.x, a.y, a.z, a.w};
        const float bv[4] = {bb.x, bb.y, bb.z, bb.w};
#pragma unroll
        for (int e = 0; e < 4; e++) {
            uint32_t hp, lp;
            split_bf(av[e], bv[e], hp, lp);
            vh[kp][c4 + e] = hp;
            vl[kp][c4 + e] = lp;
        }
    }
    if (tid < 136) {
        int i, j;
        p2ij(tid, i, j);
        ptab[tid] = make_uchar2((unsigned char)i, (unsigned char)j);
    }
    __syncthreads();

    int ia[5][2], ja[5][2];
    float wt[5][2];
#pragma unroll
    for (int mt = 0; mt < 5; mt++) {
#pragma unroll
        for (int hw = 0; hw < 2; hw++) {
            const int row = wr * 80 + mt * 16 + gid + hw * 8;
            int i, j; float w;
            if (row == 0)        { i = 16; j = 16; w = 1.f; }
            else if (row < 17)   { i = row - 1; j = 16; w = 0.5f; }
            else if (row < PROW) { uchar2 p = ptab[row - 17]; i = p.x; j = p.y; w = C2F; }
            else                 { i = 16; j = 16; w = 0.f; }
            ia[mt][hw] = i; ja[mt][hw] = j; wt[mt][hw] = w;
        }
    }

    float acc[5][2][4];
#pragma unroll
    for (int mt = 0; mt < 5; mt++)
#pragma unroll
        for (int nt = 0; nt < 2; nt++)
#pragma unroll
            for (int e = 0; e < 4; e++) acc[mt][nt][e] = 0.f;

    for (int kss = 0; kss < 8; kss++) {
        uint32_t b_h0[2], b_h1[2], b_l0[2], b_l1[2];
#pragma unroll
        for (int nt = 0; nt < 2; nt++) {
            const int n = wc * 16 + nt * 8 + gid;
            b_h0[nt] = vh[kss * 8 + tig][n];
            b_h1[nt] = vh[kss * 8 + tig + 4][n];
            b_l0[nt] = vl[kss * 8 + tig][n];
            b_l1[nt] = vl[kss * 8 + tig + 4][n];
        }
        const int t0 = kss * 16 + 2 * tig;
        const int t2 = t0 + 8;
#pragma unroll
        for (int mt = 0; mt < 5; mt++) {
            const int i0 = ia[mt][0], j0 = ja[mt][0];
            const int i1 = ia[mt][1], j1 = ja[mt][1];
            const float w0 = wt[mt][0], w1 = wt[mt][1];
            float2 ai0 = *(const float2*)&kst[i0][t0];
            float2 aj0 = *(const float2*)&kst[j0][t0];
            float2 bi0 = *(const float2*)&kst[i0][t2];
            float2 bj0 = *(const float2*)&kst[j0][t2];
            float2 ai1 = *(const float2*)&kst[i1][t0];
            float2 aj1 = *(const float2*)&kst[j1][t0];
            float2 bi1 = *(const float2*)&kst[i1][t2];
            float2 bj1 = *(const float2*)&kst[j1][t2];
            float f00 = w0 * ai0.x * aj0.x, f01 = w0 * ai0.y * aj0.y;
            float f02 = w0 * bi0.x * bj0.x, f03 = w0 * bi0.y * bj0.y;
            float f10 = w1 * ai1.x * aj1.x, f11 = w1 * ai1.y * aj1.y;
            float f12 = w1 * bi1.x * bj1.x, f13 = w1 * bi1.y * bj1.y;
            uint32_t ah[4], al[4];
            split_bf(f00, f01, ah[0], al[0]);
            split_bf(f10, f11, ah[1], al[1]);
            split_bf(f02, f03, ah[2], al[2]);
            split_bf(f12, f13, ah[3], al[3]);
#pragma unroll
            for (int nt = 0; nt < 2; nt++) {
                MMA_BF16(acc[mt][nt], ah, b_h0[nt], b_h1[nt]);
                MMA_BF16(acc[mt][nt], ah, b_l0[nt], b_l1[nt]);
                MMA_BF16(acc[mt][nt], al, b_h0[nt], b_h1[nt]);
            }
        }
    }

    float* base = DS + (size_t)(bh * NCHUNK + ck) * SDF_P;
#pragma unroll
    for (int mt = 0; mt < 5; mt++) {
        const int ra = wr * 80 + mt * 16 + gid;
        const int rb = ra + 8;
#pragma unroll
        for (int nt = 0; nt < 2; nt++) {
            const int n = wc * 16 + nt * 8 + tig * 2;
            if (ra < PROW)
                *(float2*)&base[ra * HDIM + n] =
                    make_float2(acc[mt][nt][0], acc[mt][nt][1]);
            if (rb < PROW)
                *(float2*)&base[rb * HDIM + n] =
                    make_float2(acc[mt][nt][2], acc[mt][nt][3]);
        }
    }
}

// ---------------------------------------------------------------------------
// Kernel B: exclusive scan over packed rows (153) into g_SP (R15 proven).
// ---------------------------------------------------------------------------
__global__ void scan_kernel(const float* __restrict__ DS, float* __restrict__ SP,
                            float* __restrict__ kv_out) {
    const int bh = blockIdx.y;
    const int e4 = blockIdx.x * 256 + threadIdx.x;
    if (e4 >= PROW * 16) return;
    const int dp = e4 >> 4, f0 = (e4 & 15) * 4;

    int pi = 0, pj = 0;
    float scale = 1.f;
    if (dp >= 17) {
        p2ij(dp - 17, pi, pj);
        scale = (pi == pj) ? 1.f : 2.f;
    }

    const float* src = DS + (size_t)bh * NCHUNK * SDF_P + (size_t)dp * HDIM + f0;
    float* dst = SP + (size_t)bh * NCHUNK * SDF_P + (size_t)dp * HDIM + f0;
    float4 run = make_float4(0.f, 0.f, 0.f, 0.f);
#pragma unroll
    for (int c = 0; c < NCHUNK; c++) {
        float4 v = *(const float4*)(src + (size_t)c * SDF_P);
        *(float4*)(dst + (size_t)c * SDF_P) =
            make_float4(run.x * scale, run.y * scale, run.z * scale, run.w * scale);
        run.x += v.x; run.y += v.y; run.z += v.z; run.w += v.w;
    }
    if (kv_out) {
        float* kb = kv_out + (size_t)bh * (HDIM * FEAT);
        const float rv[4] = {run.x, run.y, run.z, run.w};
        if (dp < 17) {
#pragma unroll
            for (int ff = 0; ff < 4; ff++)
                kb[(size_t)(f0 + ff) * FEAT + dp] = rv[ff];
        } else {
            const int d1 = 17 + pi * 16 + pj, d2 = 17 + pj * 16 + pi;
#pragma unroll
            for (int ff = 0; ff < 4; ff++) {
                kb[(size_t)(f0 + ff) * FEAT + d1] = rv[ff];
                kb[(size_t)(f0 + ff) * FEAT + d2] = rv[ff];
            }
        }
    }
}

// ---------------------------------------------------------------------------
// Kernel C: inter-chunk bf16x3 MMA over PACKED S (10 k-steps) + intra-chunk
// causal via two-stage MMA (scores -> poly/mask -> P@V), RMSNorm + g. (R15)
// ---------------------------------------------------------------------------
#define AK_QS(r,c)     dyn[(r)*17+(c)]                 // q*SC, col16 = 1.0
#define ATTN_SMEM      (16064*4)                       // 64,256 bytes
#define AK_SHW(b,rp,n) shw[(b)*576+(rp)*72+(n)]
#define AK_SLW(b,rp,n) slw[(b)*576+(rp)*72+(n)]

__device__ __forceinline__ float qfeatp(const float* dyn, const uchar2* ptab,
                                        int r, int d) {
    if (d == 0) return 1.0f;
    if (d < 17) return AK_QS(r, d - 1) * 1.1892071150027210f;   // 0.5/SC folded
    if (d < PROW) {
        const uchar2 ij = ptab[d - 17];
        return AK_QS(r, ij.x) * AK_QS(r, ij.y);
    }
    return 0.f;
}

__global__ __launch_bounds__(256, 2)
void attn_out_kernel(const float* __restrict__ Q, const float* __restrict__ Km,
                     const float* __restrict__ V, const float* __restrict__ Sprev,
                     const float* __restrict__ g, float* __restrict__ Y) {
    extern __shared__ float dyn[];
    __shared__ uchar2 ptab[136];
    uint32_t* kh = (uint32_t*)(dyn + 2176);    // [128][9]
    uint32_t* kl = (uint32_t*)(dyn + 3328);    // [128][9]
    uint32_t* vh = (uint32_t*)(dyn + 4480);    // [64][72]
    uint32_t* vl = (uint32_t*)(dyn + 9088);    // [64][72]
    uint32_t* shw = (uint32_t*)(dyn + 13696);
    uint32_t* slw = (uint32_t*)(dyn + 14848);
    float* gs = dyn + 16000;
    const int ck = blockIdx.x;
    const int bh = blockIdx.y;
    const int b = bh >> 4, h = bh & 15;
    const int tid = threadIdx.x;
    const int warp = tid >> 5, lane = tid & 31;
    const int gid = lane >> 2, tig = lane & 3;
    const int tok0 = b * SEQ + ck * CHUNK;
    const float SC  = 0.4204482076268573f;    // sqrt(1/(4*sqrt2))
    const float DOT = 2.3784142300054421f;    // 1/SC
    const float* Sp = Sprev + (size_t)(bh * NCHUNK + ck) * SDF_P;

    // ---- stage Q (scaled, padded) + K (packed bf16 dim-pairs, stride 9) ----
    for (int t = tid; t < 512; t += 256) {
        int r = t >> 2, c4 = (t & 3) << 2;
        float4 qv = *(const float4*)&Q[(size_t)(tok0 + r) * QKDIM + h * FDIM + c4];
        AK_QS(r, c4 + 0) = qv.x * SC; AK_QS(r, c4 + 1) = qv.y * SC;
        AK_QS(r, c4 + 2) = qv.z * SC; AK_QS(r, c4 + 3) = qv.w * SC;
        float4 kv = *(const float4*)&Km[(size_t)(tok0 + r) * QKDIM + h * FDIM + c4];
        uint32_t hp, lp;
        split_bf(kv.x, kv.y, hp, lp);
        kh[r * 9 + (c4 >> 1)] = hp; kl[r * 9 + (c4 >> 1)] = lp;
        split_bf(kv.z, kv.w, hp, lp);
        kh[r * 9 + (c4 >> 1) + 1] = hp; kl[r * 9 + (c4 >> 1) + 1] = lp;
    }
    if (tid < 128) AK_QS(tid, 16) = 1.0f;
    // ---- stage V packed bf16 token-pairs (hi/lo) ----
    for (int t = tid; t < 1024; t += 256) {
        int kp = t >> 4, c4 = (t & 15) << 2;
        float4 a = *(const float4*)&V[(size_t)(tok0 + 2 * kp) * VDIM + h * HDIM + c4];
        float4 bb = *(const float4*)&V[(size_t)(tok0 + 2 * kp + 1) * VDIM + h * HDIM + c4];
        const float av[4] = {a.x, a.y, a.z, a.w};
        const float bv[4] = {bb.x, bb.y, bb.z, bb.w};
#pragma unroll
        for (int e = 0; e < 4; e++) {
            uint32_t hp, lp;
            split_bf(av[e], bv[e], hp, lp);
            vh[kp * 72 + c4 + e] = hp;
            vl[kp * 72 + c4 + e] = lp;
        }
    }
    if (tid < 64) gs[tid] = g[tid];
    if (tid < 136) {
        int i, j;
        p2ij(tid, i, j);
        ptab[tid] = make_uchar2((unsigned char)i, (unsigned char)j);
    }
    {   // S tile for step 0
#pragma unroll
        for (int q = 0; q < 2; q++) {
            const int id = tid + q * 256;
            const int rp = id >> 6, n = id & 63;
            const int fr = 2 * rp;
            float v0 = Sp[fr * HDIM + n];
            float v1 = Sp[(fr + 1) * HDIM + n];
            uint32_t hp, lp;
            split_bf(v0, v1, hp, lp);
            AK_SHW(0, rp, n) = hp;
            AK_SLW(0, rp, n) = lp;
        }
    }
    __syncthreads();

    float acc[8][4];
#pragma unroll
    for (int nt = 0; nt < 8; nt++)
#pragma unroll
        for (int e = 0; e < 4; e++) acc[nt][e] = 0.f;

    const int r0 = warp * 16 + gid;
    const int r1 = r0 + 8;

    // ---- inter-chunk: y += qf @ S_packed via bf16x3 MMA, 10 k-steps ----
    int buf = 0;
    for (int s = 0; s < 10; s++) {
        float p00 = 0.f, p01 = 0.f, p10 = 0.f, p11 = 0.f;
        int rpA = 0, nA = 0, rpB = 0, nB = 0;
        if (s < 9) {
            const int fb = 16 * (s + 1);
            int idA = tid;           rpA = idA >> 6; nA = idA & 63;
            int idB = tid + 256;     rpB = idB >> 6; nB = idB & 63;
            int frA = fb + 2 * rpA, frB = fb + 2 * rpB;
            if (frA < PROW)     p00 = Sp[frA * HDIM + nA];
            if (frA + 1 < PROW) p01 = Sp[(frA + 1) * HDIM + nA];
            if (frB < PROW)     p10 = Sp[frB * HDIM + nB];
            if (frB + 1 < PROW) p11 = Sp[(frB + 1) * HDIM + nB];
        }
        const int da = 16 * s + 2 * tig;
        const int db = da + 8;
        float f00 = qfeatp(dyn, ptab, r0, da),  f01 = qfeatp(dyn, ptab, r0, da + 1);
        float f10 = qfeatp(dyn, ptab, r1, da),  f11 = qfeatp(dyn, ptab, r1, da + 1);
        float f02 = qfeatp(dyn, ptab, r0, db),  f03 = qfeatp(dyn, ptab, r0, db + 1);
        float f12 = qfeatp(dyn, ptab, r1, db),  f13 = qfeatp(dyn, ptab, r1, db + 1);
        uint32_t ah[4], al[4];
        split_bf(f00, f01, ah[0], al[0]);
        split_bf(f10, f11, ah[1], al[1]);
        split_bf(f02, f03, ah[2], al[2]);
        split_bf(f12, f13, ah[3], al[3]);
#pragma unroll
        for (int nt = 0; nt < 8; nt++) {
            const int n = nt * 8 + gid;
            uint32_t bh0 = AK_SHW(buf, tig, n);
            uint32_t bh1 = AK_SHW(buf, tig + 4, n);
            uint32_t bl0 = AK_SLW(buf, tig, n);
            uint32_t bl1 = AK_SLW(buf, tig + 4, n);
            MMA_BF16(acc[nt], ah, bh0, bh1);
            MMA_BF16(acc[nt], ah, bl0, bl1);
            MMA_BF16(acc[nt], al, bh0, bh1);
        }
        if (s < 9) {
            const int nb = buf ^ 1;
            uint32_t hp, lp;
            split_bf(p00, p01, hp, lp);
            AK_SHW(nb, rpA, nA) = hp;
            AK_SLW(nb, rpA, nA) = lp;
            split_bf(p10, p11, hp, lp);
            AK_SHW(nb, rpB, nB) = hp;
            AK_SLW(nb, rpB, nB) = lp;
            __syncthreads();
            buf = nb;
        }
    }

    // ---- intra-chunk causal via MMA: scores -> poly/mask -> P@V ----
    uint32_t qah[4], qal[4];
    split_bf(AK_QS(r0, 2 * tig),     AK_QS(r0, 2 * tig + 1),     qah[0], qal[0]);
    split_bf(AK_QS(r1, 2 * tig),     AK_QS(r1, 2 * tig + 1),     qah[1], qal[1]);
    split_bf(AK_QS(r0, 2 * tig + 8), AK_QS(r0, 2 * tig + 9),     qah[2], qal[2]);
    split_bf(AK_QS(r1, 2 * tig + 8), AK_QS(r1, 2 * tig + 9),     qah[3], qal[3]);

    for (int s = 0; s <= warp; s++) {
        float sc[2][4];
#pragma unroll
        for (int tt = 0; tt < 2; tt++) {
#pragma unroll
            for (int e = 0; e < 4; e++) sc[tt][e] = 0.f;
            const int tokbase = s * 16 + tt * 8;
            uint32_t bh0 = kh[(tokbase + gid) * 9 + tig];
            uint32_t bh1 = kh[(tokbase + gid) * 9 + tig + 4];
            uint32_t bl0 = kl[(tokbase + gid) * 9 + tig];
            uint32_t bl1 = kl[(tokbase + gid) * 9 + tig + 4];
            MMA_BF16(sc[tt], qah, bh0, bh1);
            MMA_BF16(sc[tt], qah, bl0, bl1);
            MMA_BF16(sc[tt], qal, bh0, bh1);
        }
        const bool diag = (s == warp);
#pragma unroll
        for (int tt = 0; tt < 2; tt++)
#pragma unroll
            for (int e = 0; e < 4; e++) {
                const float sd = sc[tt][e] * DOT;
                float A = fmaf(sd, 0.25f, 1.0f);
                A = fmaf(sd * sd, 0.03125f, A);
                if (diag) {
                    const int tok = tt * 8 + 2 * tig + (e & 1);
                    const int row = gid + ((e >> 1) << 3);
                    A = (tok <= row) ? A : 0.f;
                }
                sc[tt][e] = A;
            }
        uint32_t pah[4], pal[4];
        split_bf(sc[0][0], sc[0][1], pah[0], pal[0]);
        split_bf(sc[0][2], sc[0][3], pah[1], pal[1]);
        split_bf(sc[1][0], sc[1][1], pah[2], pal[2]);
        split_bf(sc[1][2], sc[1][3], pah[3], pal[3]);
#pragma unroll
        for (int ft = 0; ft < 8; ft++) {
            const int f = ft * 8 + gid;
            uint32_t vb0 = vh[(s * 8 + tig) * 72 + f];
            uint32_t vb1 = vh[(s * 8 + tig + 4) * 72 + f];
            uint32_t vc0 = vl[(s * 8 + tig) * 72 + f];
            uint32_t vc1 = vl[(s * 8 + tig + 4) * 72 + f];
            MMA_BF16(acc[ft], pah, vb0, vb1);
            MMA_BF16(acc[ft], pah, vc0, vc1);
            MMA_BF16(acc[ft], pal, vb0, vb1);
        }
    }

    // ---- RMSNorm (reduce across tig lanes) + gate + store ----
    float ss0 = 0.f, ss1 = 0.f;
#pragma unroll
    for (int nt = 0; nt < 8; nt++) {
        ss0 = fmaf(acc[nt][0], acc[nt][0], ss0);
        ss0 = fmaf(acc[nt][1], acc[nt][1], ss0);
        ss1 = fmaf(acc[nt][2], acc[nt][2], ss1);
        ss1 = fmaf(acc[nt][3], acc[nt][3], ss1);
    }
    ss0 += __shfl_xor_sync(0xffffffffu, ss0, 1);
    ss0 += __shfl_xor_sync(0xffffffffu, ss0, 2);
    ss1 += __shfl_xor_sync(0xffffffffu, ss1, 1);
    ss1 += __shfl_xor_sync(0xffffffffu, ss1, 2);
    const float rms0 = rsqrtf(ss0 * (1.0f / 64.0f) + 1e-5f);
    const float rms1 = rsqrtf(ss1 * (1.0f / 64.0f) + 1e-5f);
    float* y0 = Y + (size_t)(tok0 + r0) * VDIM + h * HDIM;
    float* y1 = Y + (size_t)(tok0 + r1) * VDIM + h * HDIM;
#pragma unroll
    for (int nt = 0; nt < 8; nt++) {
        const int c = nt * 8 + tig * 2;
        float2 o0, o1;
        o0.x = acc[nt][0] * rms0 * gs[c];
        o0.y = acc[nt][1] * rms0 * gs[c + 1];
        o1.x = acc[nt][2] * rms1 * gs[c];
        o1.y = acc[nt][3] * rms1 * gs[c + 1];
        *(float2*)&y0[c] = o0;
        *(float2*)&y1[c] = o1;
    }
}

// ---------------------------------------------------------------------------
extern "C" void kernel_launch(void* const* d_in, const int* in_sizes, int n_in,
                              void* d_out, int out_size) {
    const float* X  = (const float*)d_in[0];
    const float* Wq = (const float*)d_in[1];
    const float* Wk = (const float*)d_in[2];
    const float* Wv = (const float*)d_in[3];
    const float* Wo = (const float*)d_in[4];
    const float* g  = (const float*)d_in[5];
    float* out = (float*)d_out;

    float *Qb, *Kb, *Vb, *Yb, *Sb, *SPb;
    cudaGetSymbolAddress((void**)&Qb, g_Q);
    cudaGetSymbolAddress((void**)&Kb, g_K);
    cudaGetSymbolAddress((void**)&Vb, g_V);
    cudaGetSymbolAddress((void**)&Yb, g_Y);
    cudaGetSymbolAddress((void**)&Sb, g_DS);
    cudaGetSymbolAddress((void**)&SPb, g_SP);

    static int attn_smem_set = 0;
    if (!attn_smem_set) {
        cudaFuncSetAttribute(attn_out_kernel,
                             cudaFuncAttributeMaxDynamicSharedMemorySize,
                             ATTN_SMEM);
        attn_smem_set = 1;
    }

    // Projections (separate launches — proven fastest config)
    tgemm_nt<<<dim3(NTOK / 128, QKDIM / 128), 128>>>(X, Wq, Qb, NTOK, QKDIM, DMODEL);
    tgemm_nt<<<dim3(NTOK / 128, QKDIM / 128), 128>>>(X, Wk, Kb, NTOK, QKDIM, DMODEL);
    tgemm_nt<<<dim3(NTOK / 128, VDIM / 128),  128>>>(X, Wv, Vb, NTOK, VDIM,  DMODEL);

    // Chunked linear attention (packed symmetric states, all-MMA)
    float* kv_out = (out_size >= OUT_ELEMS + KV_ELEMS) ? (out + OUT_ELEMS) : nullptr;
    state_mma_kernel<<<dim3(NCHUNK, BATCH * NHEADS), 256>>>(Kb, Vb, Sb);
    scan_kernel<<<dim3((PROW * 16 + 255) / 256, BATCH * NHEADS), 256>>>(
        Sb, SPb, kv_out);
    attn_out_kernel<<<dim3(NCHUNK, BATCH * NHEADS), 256, ATTN_SMEM>>>(
        Qb, Kb, Vb, SPb, g, Yb);

    // Output projection
    tgemm_nt<<<dim3(NTOK / 128, DMODEL / 128), 128>>>(Yb, Wo, out, NTOK, DMODEL, DMODEL);
}